// round 12
// baseline (speedup 1.0000x reference)
#include <cuda_runtime.h>
#include <cuda_fp16.h>
#include <cstdint>

#define B_    256
#define T_    500
#define I_    700
#define O_    400
#define M_    (B_ * T_)        // 128000
#define KPAD  704
#define NPAD  448
#define MT    64               // CTA tile M
#define NT    224              // CTA tile N
#define KCH   32               // k per chunk
#define NCH   22               // 704/32
#define NTHR  512

#define WSCALE     4096.0f          // 2^12, exact
#define WSCALE_INV 0.000244140625f  // 2^-12, exact

// ---- device scratch ----
__device__ float  g_h [(size_t)M_ * O_];
__device__ __half g_W0[(size_t)NPAD * KPAD];
__device__ __half g_W1[(size_t)NPAD * KPAD];

// ---- smem geometry ----
#define ROWB     80
#define A32_BUF  8192                     // 64 rows x 128B fp32
#define SA_SPL   (MT * ROWB)              // 5120
#define SB_SPL   (NT * ROWB)              // 17920
#define SB_STAGE (2 * SB_SPL)             // 35840
#define OFF_A32  0
#define OFF_SA   (2 * A32_BUF)            // 16384
#define OFF_SB   (OFF_SA + 2 * SA_SPL)    // 26624
#define SMEM_SZ  (OFF_SB + 3 * SB_STAGE)  // 134144

// ============================ PTX helpers ============================
__device__ __forceinline__ uint32_t smem_u32(const void* p) {
    uint32_t a;
    asm("{ .reg .u64 t; cvta.to.shared.u64 t, %1; cvt.u32.u64 %0, t; }" : "=r"(a) : "l"(p));
    return a;
}
__device__ __forceinline__ void cp16(uint32_t dst, const void* src) {
    asm volatile("cp.async.cg.shared.global [%0], [%1], 16;" :: "r"(dst), "l"(src) : "memory");
}
__device__ __forceinline__ void ldsm_x4(uint32_t* r, uint32_t addr) {
    asm volatile("ldmatrix.sync.aligned.m8n8.x4.shared.b16 {%0,%1,%2,%3}, [%4];"
        : "=r"(r[0]), "=r"(r[1]), "=r"(r[2]), "=r"(r[3]) : "r"(addr));
}
__device__ __forceinline__ void ldsm_x2(uint32_t* r, uint32_t addr) {
    asm volatile("ldmatrix.sync.aligned.m8n8.x2.shared.b16 {%0,%1}, [%2];"
        : "=r"(r[0]), "=r"(r[1]) : "r"(addr));
}
__device__ __forceinline__ void mma16816(float* d, const uint32_t* a, const uint32_t* b) {
    asm volatile("mma.sync.aligned.m16n8k16.row.col.f32.f16.f16.f32 "
        "{%0,%1,%2,%3}, {%4,%5,%6,%7}, {%8,%9}, {%0,%1,%2,%3};"
        : "+f"(d[0]), "+f"(d[1]), "+f"(d[2]), "+f"(d[3])
        : "r"(a[0]), "r"(a[1]), "r"(a[2]), "r"(a[3]), "r"(b[0]), "r"(b[1]));
}
// warp tile 16M x 56N: aF[4] (1 m16-tile), bF[14] (6 n8-tiles via x4 + 1 via x2)
__device__ __forceinline__ void mma_tile(float* p, const uint32_t* aF, const uint32_t* bF) {
    #pragma unroll
    for (int nt = 0; nt < 7; nt++) {
        const uint32_t* b = (nt < 6) ? (bF + (nt >> 1) * 4 + (nt & 1) * 2) : (bF + 12);
        mma16816(p + nt * 4, aF, b);
    }
}

// ============================ kernels ============================

// W pre-split: scale by 2^12 (exact), then 2-way fp16 split. (Unchanged, proven.)
__global__ void convert_split2_W(const float* __restrict__ src,
                                 __half* __restrict__ d0,
                                 __half* __restrict__ d1) {
    size_t m = blockIdx.x;
    const float* s = src + m * I_;
    size_t off = m * KPAD;
    for (int k = threadIdx.x; k < I_; k += blockDim.x) {
        float a = s[k] * WSCALE;
        __half h0 = __float2half_rn(a);
        float r1 = a - __half2float(h0);
        d0[off + k] = h0;
        d1[off + k] = __float2half_rn(r1);
    }
}

// Fused fp32-A-load + 2-way-fp16-split + 3-pass mma.sync GEMM.
// CTA 64M x 224N, 16 warps (4M x 4N), warp tile 16x56 -> 4 warps/SMSP.
// Convert of chunk c+1 is issued AFTER chunk c's compute (pipelined).
__global__ __launch_bounds__(NTHR, 1) void snn_gemm_mma(const float* __restrict__ gA) {
    extern __shared__ char smem[];
    const uint32_t sb = smem_u32(smem);
    const int tid    = threadIdx.x;
    const int lane   = tid & 31;
    const int wid    = tid >> 5;
    const int warp_m = wid & 3;
    const int warp_n = wid >> 2;
    const int m0     = blockIdx.y * MT;
    const int n0     = blockIdx.x * NT;

    const __half* gB[2] = {g_W0, g_W1};

    // ldmatrix bases
    const uint32_t aoff = (uint32_t)(warp_m * 16 + (lane & 15)) * ROWB + ((lane >> 4) << 4);
    const uint32_t boff_col = (uint32_t)(((lane >> 3) & 1) << 4);
    const uint32_t brow     = (uint32_t)(warp_n * 56 + (lane & 7) + ((lane >> 4) << 3));
    const uint32_t brow_x2  = (uint32_t)(warp_n * 56 + 48 + (lane & 7));
    const uint32_t boff_x2  = brow_x2 * ROWB + (uint32_t)(((lane >> 3) & 1) << 4);

    float acc[28];
    #pragma unroll
    for (int e = 0; e < 28; e++) acc[e] = 0.0f;

    // ---- chunk loader: 2304 cp16 over 512 threads ----
    auto load_chunk = [&](int c) {
        const uint32_t abuf = sb + OFF_A32 + (uint32_t)(c & 1) * A32_BUF;
        const uint32_t bbuf = sb + OFF_SB + (uint32_t)(c % 3) * SB_STAGE;
        #pragma unroll
        for (int it = 0; it < 5; it++) {
            int idx = tid + it * NTHR;
            if (idx < 512) {                       // A fp32: 64 rows x 8 slots of 16B
                int r = idx >> 3, sl = idx & 7;
                uint32_t dst = abuf + r * 128 + sl * 16;
                if (c == NCH - 1 && sl == 7) {     // k 700..703 pad
                    *reinterpret_cast<uint4*>(smem + (dst - sb)) = make_uint4(0, 0, 0, 0);
                } else {
                    const void* src = (const char*)gA + ((size_t)(m0 + r) * I_ + c * KCH) * 4 + sl * 16;
                    cp16(dst, src);
                }
            } else if (idx < 2304) {               // B: 2 splits x 224 rows x 4 slots
                int q = idx - 512;
                int j = q / 896, rem = q % 896;
                int r = rem >> 2, sl = rem & 3;
                const void* src = (const char*)gB[j] + ((size_t)(n0 + r) * KPAD + c * KCH) * 2 + sl * 16;
                cp16(bbuf + j * SB_SPL + r * ROWB + sl * 16, src);
            }
        }
        asm volatile("cp.async.commit_group;" ::: "memory");
    };

    // ---- A convert: 2048 fp32 over 512 threads = 4 elems each ----
    auto convert_A = [&](int c) {
        const char* a32 = smem + OFF_A32 + (c & 1) * A32_BUF;
        int r = tid >> 3, blk = tid & 7;           // row, 4-elem block
        float4 v = *reinterpret_cast<const float4*>(a32 + r * 128 + blk * 16);
        float av[4] = {v.x, v.y, v.z, v.w};
        uint16_t s0[4], s1[4];
        #pragma unroll
        for (int i = 0; i < 4; i++) {
            float a = av[i];
            __half h0 = __float2half_rn(a);
            float r1 = a - __half2float(h0);
            __half h1 = __float2half_rn(r1);
            s0[i] = __half_as_ushort(h0);
            s1[i] = __half_as_ushort(h1);
        }
        uint32_t doff = r * ROWB + blk * 8;
        uint2 w0, w1;
        w0.x = (uint32_t)s0[0] | ((uint32_t)s0[1] << 16);
        w0.y = (uint32_t)s0[2] | ((uint32_t)s0[3] << 16);
        w1.x = (uint32_t)s1[0] | ((uint32_t)s1[1] << 16);
        w1.y = (uint32_t)s1[2] | ((uint32_t)s1[3] << 16);
        *reinterpret_cast<uint2*>(smem + OFF_SA + 0 * SA_SPL + doff) = w0;
        *reinterpret_cast<uint2*>(smem + OFF_SA + 1 * SA_SPL + doff) = w1;
    };

    // prologue
    load_chunk(0);
    load_chunk(1);
    asm volatile("cp.async.wait_group 1;" ::: "memory");   // chunk 0 done
    __syncthreads();
    convert_A(0);

    for (int c = 0; c < NCH; c++) {
        __syncthreads();   // SA[c%2] converted, SB[c%3] loaded & visible

        // ---- compute chunk c ----
        const uint32_t aB = sb + OFF_SA + aoff;
        const uint32_t bB = sb + OFF_SB + (uint32_t)(c % 3) * SB_STAGE;

        float p[28];
        #pragma unroll
        for (int e = 0; e < 28; e++) p[e] = 0.0f;

        #pragma unroll
        for (int step = 0; step < 2; step++) {
            const uint32_t ks = step * 32;
            uint32_t aF0[4], aF1[4], bF0[14], bF1[14];

            ldsm_x4(aF0, aB + 0 * SA_SPL + ks);
            ldsm_x4(aF1, aB + 1 * SA_SPL + ks);
            #pragma unroll
            for (int q = 0; q < 3; q++) {
                uint32_t ro = (brow + q * 16) * ROWB + boff_col;
                ldsm_x4(bF0 + 4 * q, bB + 0 * SB_SPL + ro + ks);
                ldsm_x4(bF1 + 4 * q, bB + 1 * SB_SPL + ro + ks);
            }
            ldsm_x2(bF0 + 12, bB + 0 * SB_SPL + boff_x2 + ks);
            ldsm_x2(bF1 + 12, bB + 1 * SB_SPL + boff_x2 + ks);

            mma_tile(p, aF0, bF0);   // A0*B0
            mma_tile(p, aF0, bF1);   // A0*B1
            mma_tile(p, aF1, bF0);   // A1*B0
        }

        #pragma unroll
        for (int e = 0; e < 28; e++) acc[e] = __fadd_rn(acc[e], p[e]);

        // ---- prefetch + pipelined convert of next chunk ----
        if (c + 2 < NCH) load_chunk(c + 2);
        if (c + 1 < NCH) {
            if (c + 2 < NCH) asm volatile("cp.async.wait_group 1;" ::: "memory");
            else             asm volatile("cp.async.wait_group 0;" ::: "memory");
            __syncthreads();          // A32[(c+1)%2] visible to all
            convert_A(c + 1);
        }
    }

    // ---- store (undo W scale by exact 2^-12) ----
    #pragma unroll
    for (int nt = 0; nt < 7; nt++) {
        const float* e = acc + nt * 4;
        int m = m0 + warp_m * 16 + (lane >> 2);
        int n = n0 + warp_n * 56 + nt * 8 + (lane & 3) * 2;
        if (n < O_) {
            *reinterpret_cast<float2*>(g_h + (size_t)m * O_ + n) =
                make_float2(e[0] * WSCALE_INV, e[1] * WSCALE_INV);
            *reinterpret_cast<float2*>(g_h + (size_t)(m + 8) * O_ + n) =
                make_float2(e[2] * WSCALE_INV, e[3] * WSCALE_INV);
        }
    }
}

// One thread per (b, o) neuron; sequential over t. Deeper unroll for MLP.
__global__ __launch_bounds__(256) void snn_scan_kernel(float* __restrict__ out) {
    int idx = blockIdx.x * blockDim.x + threadIdx.x;
    if (idx >= B_ * O_) return;
    int b = idx / O_;
    int o = idx - b * O_;

    const float* hp = g_h + (size_t)b * T_ * O_ + o;
    float* op = out + (size_t)b * T_ * O_ + o;

    float syn = 0.0f, mem = 0.0f;
    #pragma unroll 10
    for (int t = 0; t < T_; t++) {
        float ht = __ldg(hp + (size_t)t * O_);
        float s  = (mem > 1.0f) ? 1.0f : 0.0f;
        op[(size_t)t * O_] = s;
        float nsyn = __fmaf_rn(0.9f, syn, ht);
        float bmv  = __fmaf_rn(0.85f, mem, syn);
        mem = __fmul_rn(bmv, __fadd_rn(1.0f, -s));
        syn = nsyn;
    }
}

// ============================ host ============================
extern "C" void kernel_launch(void* const* d_in, const int* in_sizes, int n_in,
                              void* d_out, int out_size) {
    const float* inputs = (const float*)d_in[0];  // [256,500,700] f32
    const float* W      = (const float*)d_in[1];  // [400,700]     f32
    float* out          = (float*)d_out;          // [256,500,400] f32

    void *pW0, *pW1;
    cudaGetSymbolAddress(&pW0, g_W0);
    cudaGetSymbolAddress(&pW1, g_W1);

    convert_split2_W<<<O_, 256>>>(W, (__half*)pW0, (__half*)pW1);

    cudaFuncSetAttribute(snn_gemm_mma, cudaFuncAttributeMaxDynamicSharedMemorySize, SMEM_SZ);
    dim3 grid(2, M_ / MT);    // 2 N-tiles x 2000 M-tiles
    snn_gemm_mma<<<grid, NTHR, SMEM_SZ>>>(inputs);

    int n_neurons = B_ * O_;
    snn_scan_kernel<<<(n_neurons + 255) / 256, 256>>>(out);
}

// round 13
// speedup vs baseline: 1.2118x; 1.2118x over previous
#include <cuda_runtime.h>
#include <cuda_fp16.h>
#include <cstdint>

#define B_    256
#define T_    500
#define I_    700
#define O_    400
#define M_    (B_ * T_)        // 128000
#define KPAD  704
#define NPAD  448
#define MT    64               // CTA tile M
#define KCH   64               // k per chunk
#define NCH   11               // 704/64
#define NTHR  256

#define WSCALE     4096.0f          // 2^12, exact
#define WSCALE_INV 0.000244140625f  // 2^-12, exact

// ---- device scratch ----
__device__ float  g_h [(size_t)M_ * O_];
__device__ __half g_W0[(size_t)NPAD * KPAD];
__device__ __half g_W1[(size_t)NPAD * KPAD];

// ---- smem geometry ----
#define ROWB     144                      // 128B k-data + 16B pad
#define A32_BUF  16384                    // 64 rows x 256B fp32
#define SA_SPL   (MT * ROWB)              // 9216  (single-buffered, 2 splits)
#define SB_SPL   (224 * ROWB)             // 32256 per split (max path)
#define SB_STAGE (2 * SB_SPL)             // 64512
#define OFF_A32  0                        // 2 bufs -> 32768
#define OFF_SA   (2 * A32_BUF)            // 32768
#define OFF_SB   (OFF_SA + 2 * SA_SPL)    // 51200
#define SMEM_SZ  (OFF_SB + 2 * SB_STAGE)  // 180224

// ============================ PTX helpers ============================
__device__ __forceinline__ uint32_t smem_u32(const void* p) {
    uint32_t a;
    asm("{ .reg .u64 t; cvta.to.shared.u64 t, %1; cvt.u32.u64 %0, t; }" : "=r"(a) : "l"(p));
    return a;
}
__device__ __forceinline__ void cp16(uint32_t dst, const void* src) {
    asm volatile("cp.async.cg.shared.global [%0], [%1], 16;" :: "r"(dst), "l"(src) : "memory");
}
__device__ __forceinline__ void ldsm_x4(uint32_t* r, uint32_t addr) {
    asm volatile("ldmatrix.sync.aligned.m8n8.x4.shared.b16 {%0,%1,%2,%3}, [%4];"
        : "=r"(r[0]), "=r"(r[1]), "=r"(r[2]), "=r"(r[3]) : "r"(addr));
}
__device__ __forceinline__ void ldsm_x2(uint32_t* r, uint32_t addr) {
    asm volatile("ldmatrix.sync.aligned.m8n8.x2.shared.b16 {%0,%1}, [%2];"
        : "=r"(r[0]), "=r"(r[1]) : "r"(addr));
}
__device__ __forceinline__ void mma16816(float* d, const uint32_t* a, const uint32_t* b) {
    asm volatile("mma.sync.aligned.m16n8k16.row.col.f32.f16.f16.f32 "
        "{%0,%1,%2,%3}, {%4,%5,%6,%7}, {%8,%9}, {%0,%1,%2,%3};"
        : "+f"(d[0]), "+f"(d[1]), "+f"(d[2]), "+f"(d[3])
        : "r"(a[0]), "r"(a[1]), "r"(a[2]), "r"(a[3]), "r"(b[0]), "r"(b[1]));
}

// warp tile 32M x (WNT*8)N
template<int WNT>
__device__ __forceinline__ void mma_tileT(float* p, const uint32_t* aF, const uint32_t* bF) {
    #pragma unroll
    for (int mt = 0; mt < 2; mt++)
        #pragma unroll
        for (int nt = 0; nt < WNT; nt++) {
            const uint32_t* b = (nt < (WNT & ~1)) ? (bF + (nt >> 1) * 4 + (nt & 1) * 2)
                                                  : (bF + (WNT - 1) * 2);
            mma16816(p + (mt * WNT + nt) * 4, aF + mt * 4, b);
        }
}

// ============================ kernels ============================

// W pre-split: scale by 2^12 (exact), then 2-way fp16 split. (Proven.)
__global__ void convert_split2_W(const float* __restrict__ src,
                                 __half* __restrict__ d0,
                                 __half* __restrict__ d1) {
    size_t m = blockIdx.x;
    const float* s = src + m * I_;
    size_t off = m * KPAD;
    for (int k = threadIdx.x; k < I_; k += blockDim.x) {
        float a = s[k] * WSCALE;
        __half h0 = __float2half_rn(a);
        float r1 = a - __half2float(h0);
        d0[off + k] = h0;
        d1[off + k] = __float2half_rn(r1);
    }
}

template<int WNT>
__device__ __forceinline__ void gemm_body(const float* __restrict__ gA,
                                          char* smem, int m0, int n0) {
    constexpr int NROWS  = WNT * 32;               // B rows this CTA loads
    constexpr int NCP16  = 1024 + 2 * NROWS * 8;   // A(1024) + B cp16 count
    constexpr int NITERS = (NCP16 + NTHR - 1) / NTHR;

    const uint32_t sb = smem_u32(smem);
    const int tid    = threadIdx.x;
    const int lane   = tid & 31;
    const int wid    = tid >> 5;
    const int warp_m = wid & 1;
    const int warp_n = wid >> 1;

    const __half* gB[2] = {g_W0, g_W1};

    const uint32_t aoff = (uint32_t)(warp_m * 32 + (lane & 15)) * ROWB + ((lane >> 4) << 4);
    const uint32_t boff_col = (uint32_t)(((lane >> 3) & 1) << 4);
    const uint32_t brow     = (uint32_t)(warp_n * (WNT * 8) + (lane & 7) + ((lane >> 4) << 3));
    const uint32_t boff_x2  = (uint32_t)(warp_n * (WNT * 8) + (WNT / 2) * 16 + (lane & 7)) * ROWB
                            + (uint32_t)(((lane >> 3) & 1) << 4);

    float acc[2 * WNT * 4];
    #pragma unroll
    for (int e = 0; e < 2 * WNT * 4; e++) acc[e] = 0.0f;

    auto load_chunk = [&](int c) {
        const int k0 = c * KCH;
        const uint32_t abuf = sb + OFF_A32 + (uint32_t)(c & 1) * A32_BUF;
        const uint32_t bbuf = sb + OFF_SB + (uint32_t)(c & 1) * SB_STAGE;
        #pragma unroll
        for (int it = 0; it < NITERS; it++) {
            int idx = tid + it * NTHR;
            if (idx < 1024) {                      // A fp32: 64 rows x 16 slots of 16B
                int r = idx >> 4, sl = idx & 15;
                uint32_t dst = abuf + r * 256 + sl * 16;
                if (c == NCH - 1 && sl == 15) {    // k 700..703 pad
                    *reinterpret_cast<uint4*>(smem + (dst - sb)) = make_uint4(0, 0, 0, 0);
                } else {
                    const void* src = (const char*)gA + ((size_t)(m0 + r) * I_ + k0) * 4 + sl * 16;
                    cp16(dst, src);
                }
            } else if (idx < NCP16) {              // B: 2 splits x NROWS x 8 slots
                int q = idx - 1024;
                int j = q / (NROWS * 8), rem = q % (NROWS * 8);
                int r = rem >> 3, sl = rem & 7;
                const void* src = (const char*)gB[j] + ((size_t)(n0 + r) * KPAD + k0) * 2 + sl * 16;
                cp16(bbuf + j * SB_SPL + r * ROWB + sl * 16, src);
            }
        }
        asm volatile("cp.async.commit_group;" ::: "memory");
    };

    // A convert: 4096 fp32 per chunk / 256 thr = 16 elems (4 float4) each
    auto convert_A = [&](int c) {
        const char* a32 = smem + OFF_A32 + (c & 1) * A32_BUF;
        int r = tid >> 2;
        #pragma unroll
        for (int i = 0; i < 4; i++) {
            int s = (tid & 3) * 4 + i;             // float4 slot 0..15
            float4 v = *reinterpret_cast<const float4*>(a32 + r * 256 + s * 16);
            float av[4] = {v.x, v.y, v.z, v.w};
            uint16_t h0[4], h1[4];
            #pragma unroll
            for (int e = 0; e < 4; e++) {
                float a = av[e];
                __half q0 = __float2half_rn(a);
                float r1 = a - __half2float(q0);
                __half q1 = __float2half_rn(r1);
                h0[e] = __half_as_ushort(q0);
                h1[e] = __half_as_ushort(q1);
            }
            uint32_t doff = r * ROWB + s * 8;      // 4 halves = 8 bytes
            uint2 w0, w1;
            w0.x = (uint32_t)h0[0] | ((uint32_t)h0[1] << 16);
            w0.y = (uint32_t)h0[2] | ((uint32_t)h0[3] << 16);
            w1.x = (uint32_t)h1[0] | ((uint32_t)h1[1] << 16);
            w1.y = (uint32_t)h1[2] | ((uint32_t)h1[3] << 16);
            *reinterpret_cast<uint2*>(smem + OFF_SA + 0 * SA_SPL + doff) = w0;
            *reinterpret_cast<uint2*>(smem + OFF_SA + 1 * SA_SPL + doff) = w1;
        }
    };

    // prologue
    load_chunk(0);
    asm volatile("cp.async.wait_group 0;" ::: "memory");
    __syncthreads();
    convert_A(0);
    __syncthreads();

    for (int c = 0; c < NCH; c++) {
        if (c + 1 < NCH) load_chunk(c + 1);        // overlaps compute below

        // ---- compute chunk c ----
        const uint32_t aB = sb + OFF_SA + aoff;
        const uint32_t bB = sb + OFF_SB + (uint32_t)(c & 1) * SB_STAGE;

        float p[2 * WNT * 4];
        #pragma unroll
        for (int e = 0; e < 2 * WNT * 4; e++) p[e] = 0.0f;

        #pragma unroll
        for (int step = 0; step < 4; step++) {
            const uint32_t ks = step * 32;
            uint32_t aF0[8], aF1[8], bF0[2 * WNT], bF1[2 * WNT];

            ldsm_x4(aF0 + 0, aB + 0 * SA_SPL + ks);
            ldsm_x4(aF0 + 4, aB + 0 * SA_SPL + 16 * ROWB + ks);
            ldsm_x4(aF1 + 0, aB + 1 * SA_SPL + ks);
            ldsm_x4(aF1 + 4, aB + 1 * SA_SPL + 16 * ROWB + ks);
            #pragma unroll
            for (int q = 0; q < WNT / 2; q++) {
                uint32_t ro = (brow + q * 16) * ROWB + boff_col;
                ldsm_x4(bF0 + 4 * q, bB + 0 * SB_SPL + ro + ks);
                ldsm_x4(bF1 + 4 * q, bB + 1 * SB_SPL + ro + ks);
            }
            if (WNT & 1) {
                ldsm_x2(bF0 + (WNT - 1) * 2, bB + 0 * SB_SPL + boff_x2 + ks);
                ldsm_x2(bF1 + (WNT - 1) * 2, bB + 1 * SB_SPL + boff_x2 + ks);
            }

            mma_tileT<WNT>(p, aF0, bF0);   // A0*B0
            mma_tileT<WNT>(p, aF0, bF1);   // A0*B1
            mma_tileT<WNT>(p, aF1, bF0);   // A1*B0
        }

        #pragma unroll
        for (int e = 0; e < 2 * WNT * 4; e++) acc[e] = __fadd_rn(acc[e], p[e]);

        if (c + 1 < NCH) {
            asm volatile("cp.async.wait_group 0;" ::: "memory");
            __syncthreads();               // chunk c+1 A32+SB visible; SA free
            convert_A(c + 1);
            __syncthreads();               // SA visible
        }
    }

    // ---- store (undo W scale by exact 2^-12) ----
    #pragma unroll
    for (int mt = 0; mt < 2; mt++) {
        #pragma unroll
        for (int nt = 0; nt < WNT; nt++) {
            const float* e = acc + (mt * WNT + nt) * 4;
            int m = m0 + warp_m * 32 + mt * 16 + (lane >> 2);
            int n = n0 + warp_n * (WNT * 8) + nt * 8 + (lane & 3) * 2;
            if (n < O_) {
                *reinterpret_cast<float2*>(g_h + (size_t)m * O_ + n) =
                    make_float2(e[0] * WSCALE_INV, e[1] * WSCALE_INV);
                *reinterpret_cast<float2*>(g_h + (size_t)(m + 8) * O_ + n) =
                    make_float2(e[2] * WSCALE_INV, e[3] * WSCALE_INV);
            }
        }
    }
}

__global__ __launch_bounds__(NTHR, 1) void snn_gemm_mma(const float* __restrict__ gA) {
    extern __shared__ char smem[];
    int m0 = blockIdx.y * MT;
    if (blockIdx.x == 0) gemm_body<7>(gA, smem, m0, 0);     // cols 0..223
    else                 gemm_body<6>(gA, smem, m0, 224);   // cols 224..415 (>=400)
}

// One thread per (b, o) neuron; sequential over t. (Proven.)
__global__ __launch_bounds__(256) void snn_scan_kernel(float* __restrict__ out) {
    int idx = blockIdx.x * blockDim.x + threadIdx.x;
    if (idx >= B_ * O_) return;
    int b = idx / O_;
    int o = idx - b * O_;

    const float* hp = g_h + (size_t)b * T_ * O_ + o;
    float* op = out + (size_t)b * T_ * O_ + o;

    float syn = 0.0f, mem = 0.0f;
    #pragma unroll 10
    for (int t = 0; t < T_; t++) {
        float ht = __ldg(hp + (size_t)t * O_);
        float s  = (mem > 1.0f) ? 1.0f : 0.0f;
        op[(size_t)t * O_] = s;
        float nsyn = __fmaf_rn(0.9f, syn, ht);
        float bmv  = __fmaf_rn(0.85f, mem, syn);
        mem = __fmul_rn(bmv, __fadd_rn(1.0f, -s));
        syn = nsyn;
    }
}

// ============================ host ============================
extern "C" void kernel_launch(void* const* d_in, const int* in_sizes, int n_in,
                              void* d_out, int out_size) {
    const float* inputs = (const float*)d_in[0];  // [256,500,700] f32
    const float* W      = (const float*)d_in[1];  // [400,700]     f32
    float* out          = (float*)d_out;          // [256,500,400] f32

    void *pW0, *pW1;
    cudaGetSymbolAddress(&pW0, g_W0);
    cudaGetSymbolAddress(&pW1, g_W1);

    convert_split2_W<<<O_, 256>>>(W, (__half*)pW0, (__half*)pW1);

    cudaFuncSetAttribute(snn_gemm_mma, cudaFuncAttributeMaxDynamicSharedMemorySize, SMEM_SZ);
    dim3 grid(2, M_ / MT);    // {224-wide, 192-wide} x 2000 M-tiles
    snn_gemm_mma<<<grid, NTHR, SMEM_SZ>>>(inputs);

    int n_neurons = B_ * O_;
    snn_scan_kernel<<<(n_neurons + 255) / 256, 256>>>(out);
}